// round 1
// baseline (speedup 1.0000x reference)
#include <cuda_runtime.h>

// Problem constants
#define B 2
#define N 2048
#define C 768
// scale = (C/NUM_HEADS)^-0.5 = 64^-0.5 = 0.125

// Scratch in device globals (no allocation allowed)
__device__ float g_part[B][16][C];   // partial column sums of X
__device__ float g_s[B][C];          // s_b = sum_n X[b,n,:]
__device__ float g_u[B][C];          // u_b = Wk s_b
__device__ float g_vpart[B][8][C];   // partials of v = Wq^T u
__device__ float g_v[B][C];          // v_b

// K1: partial column sums of X. grid (3,16,B), block 256.
// Block (bx, chunk, b): cols [bx*256, bx*256+256), rows [chunk*128, chunk*128+128)
__global__ void k_colsum_part(const float* __restrict__ X) {
    int b = blockIdx.z;
    int chunk = blockIdx.y;
    int c = blockIdx.x * 256 + threadIdx.x;
    const float* p = X + ((size_t)b * N + (size_t)chunk * 128) * C + c;
    float acc = 0.f;
#pragma unroll 8
    for (int r = 0; r < 128; ++r)
        acc += p[(size_t)r * C];
    g_part[b][chunk][c] = acc;
}

// K2: reduce 16 partials -> s. grid (3,B), block 256.
__global__ void k_colsum_reduce() {
    int b = blockIdx.y;
    int c = blockIdx.x * 256 + threadIdx.x;
    float acc = 0.f;
#pragma unroll
    for (int k = 0; k < 16; ++k)
        acc += g_part[b][k][c];
    g_s[b][c] = acc;
}

// K3: u = Wk @ s for both batches. One warp per output row j.
// Wk = W rows [768, 1536). grid 96, block 256 (8 warps).
__global__ void k_wk_matvec(const float* __restrict__ W) {
    int j = blockIdx.x * 8 + (threadIdx.x >> 5);
    int lane = threadIdx.x & 31;
    const float* row = W + (size_t)(C + j) * C;
    float a0 = 0.f, a1 = 0.f;
#pragma unroll
    for (int c = lane; c < C; c += 32) {
        float w = row[c];
        a0 += w * g_s[0][c];
        a1 += w * g_s[1][c];
    }
#pragma unroll
    for (int o = 16; o > 0; o >>= 1) {
        a0 += __shfl_down_sync(0xFFFFFFFFu, a0, o);
        a1 += __shfl_down_sync(0xFFFFFFFFu, a1, o);
    }
    if (lane == 0) {
        g_u[0][j] = a0;
        g_u[1][j] = a1;
    }
}

// K4: partials of v = Wq^T @ u. grid (3,8), block 256.
// Block (bx, jy): cols [bx*256, +256), rows j in [jy*96, +96).
// Consecutive threads read consecutive c of W[j] -> coalesced.
__global__ void k_wqT_part(const float* __restrict__ W) {
    int c = blockIdx.x * 256 + threadIdx.x;
    int j0 = blockIdx.y * 96;
    float a0 = 0.f, a1 = 0.f;
#pragma unroll 4
    for (int j = j0; j < j0 + 96; ++j) {
        float w = W[(size_t)j * C + c];
        a0 += w * g_u[0][j];
        a1 += w * g_u[1][j];
    }
    g_vpart[0][blockIdx.y][c] = a0;
    g_vpart[1][blockIdx.y][c] = a1;
}

// K5: reduce 8 partials -> v. grid (3,B), block 256.
__global__ void k_v_reduce() {
    int b = blockIdx.y;
    int c = blockIdx.x * 256 + threadIdx.x;
    float acc = 0.f;
#pragma unroll
    for (int k = 0; k < 8; ++k)
        acc += g_vpart[b][k][c];
    g_v[b][c] = acc;
}

// K6: scores[b,n] = 0.125 * dot(X[b,n,:], v[b,:]).
// One warp per row n. block 256 = 8 rows/block. grid 512 (256 per batch).
__global__ void k_scores(const float* __restrict__ X, float* __restrict__ out) {
    __shared__ float vs[C];
    int b = blockIdx.x >> 8;                 // blocks 0..255 -> b=0, 256..511 -> b=1
    int rowBase = (blockIdx.x & 255) * 8;
    for (int i = threadIdx.x; i < C; i += 256)
        vs[i] = g_v[b][i];
    __syncthreads();
    int warp = threadIdx.x >> 5;
    int lane = threadIdx.x & 31;
    int n = rowBase + warp;
    const float* x = X + ((size_t)b * N + n) * C;
    float a = 0.f;
#pragma unroll
    for (int c = lane; c < C; c += 32)
        a += x[c] * vs[c];
#pragma unroll
    for (int o = 16; o > 0; o >>= 1)
        a += __shfl_down_sync(0xFFFFFFFFu, a, o);
    if (lane == 0)
        out[b * N + n] = 0.125f * a;
}

extern "C" void kernel_launch(void* const* d_in, const int* in_sizes, int n_in,
                              void* d_out, int out_size) {
    const float* X = (const float*)d_in[0];     // [2, 2048, 768] f32
    const float* W = (const float*)d_in[1];     // [1536, 768] f32
    float* out = (float*)d_out;                 // [2, 2048] f32

    (void)in_sizes; (void)n_in; (void)out_size;

    k_colsum_part<<<dim3(3, 16, B), 256>>>(X);
    k_colsum_reduce<<<dim3(3, B), 256>>>();
    k_wk_matvec<<<96, 256>>>(W);
    k_wqT_part<<<dim3(3, 8), 256>>>(W);
    k_v_reduce<<<dim3(3, B), 256>>>();
    k_scores<<<512, 256>>>(X, out);
}